// round 13
// baseline (speedup 1.0000x reference)
#include <cuda_runtime.h>

#define W_IMG  1248
#define NROWS  768
#define SEGW   320            // outputs per warp-segment
#define NSEG   4              // 4*320 = 1280 >= 1248, tail masked
#define HALO   192
#define NT     128            // 4 warps = 4 rows per CTA (same segment)
#define C      16             // elements per thread; 192 = 12*16 exactly

__global__ __launch_bounds__(NT) void stereo_win2_kernel(
    const float* __restrict__ L,
    const float* __restrict__ R,
    float* __restrict__ out)
{
    const int tid  = threadIdx.x;
    const int lane = tid & 31;
    const int warp = tid >> 5;
    const int row  = blockIdx.x * 4 + warp;   // 192*4 = 768 rows
    const int seg  = blockIdx.y;              // 0..3

    const float* __restrict__ r = R + (size_t)row * W_IMG;
    const float* __restrict__ l = L + (size_t)row * W_IMG;
    float* __restrict__ o = out + (size_t)row * W_IMG;

    const int u0 = lane * C;                  // local coord base (0..496)
    const int j0 = seg * SEGW - HALO + u0;    // global column of this chunk
    // whole-chunk predicates (all boundaries multiples of 16)
    const bool inr  = (j0 >= 0) && (j0 + C <= W_IMG);     // r-load validity
    const bool outv = (u0 >= HALO) && (j0 + C <= W_IMG);  // output validity

    // ---- ALL loads front-batched: 8 x LDG.128, MLP=8 ----
    float rv[C];
    if (inr) {
        #pragma unroll
        for (int v = 0; v < 4; v++)
            *(float4*)(rv + 4 * v) = *(const float4*)(r + j0 + 4 * v);
    } else {
        #pragma unroll
        for (int s = 0; s < C; s++) rv[s] = 0.f;
    }
    float lv[C];
    if (outv) {
        #pragma unroll
        for (int v = 0; v < 4; v++)
            *(float4*)(lv + 4 * v) = *(const float4*)(l + j0 + 4 * v);
    }

    // ---- chunk-LOCAL inclusive scan ----
    float lpl[C], lql[C];
    float p = 0.f, q = 0.f;
    {
        float uf = (float)u0;
        #pragma unroll
        for (int s = 0; s < C; s++) {
            p += rv[s];
            q = fmaf(uf, rv[s], q);
            lpl[s] = p;
            lql[s] = q;
            uf += 1.f;
        }
    }

    // ---- width-12 sliding-window sum of chunk totals (4-deep chain) ----
    // w12(k) = sum of (p,q) over lanes k-11..k  =  s8 + shfl_up(s4, 8)
    float s2p = p + __shfl_up_sync(0xffffffffu, p, 1);
    float s2q = q + __shfl_up_sync(0xffffffffu, q, 1);
    float s4p = s2p + __shfl_up_sync(0xffffffffu, s2p, 2);
    float s4q = s2q + __shfl_up_sync(0xffffffffu, s2q, 2);
    float s8p = s4p + __shfl_up_sync(0xffffffffu, s4p, 4);
    float s8q = s4q + __shfl_up_sync(0xffffffffu, s4q, 4);
    const float wp = s8p + __shfl_up_sync(0xffffffffu, s4p, 8) - p;  // 11 full chunks
    const float wq = s8q + __shfl_up_sync(0xffffffffu, s4q, 8) - q;

    // ---- outputs in groups of 4: compute then store immediately ----
    // Producer (lane-12) term: T = u_cons*(p - lpl[s]) - (q - lql[s]),
    // u_cons = u0_prod + 192 + s. Consumer: S = u*(lpl+wp) - (lql+wq) + bT.
    {
        float uA = (float)(u0 + HALO);        // producer-side consumer coordinate
        float uB = (float)u0;                 // own coordinate
        #pragma unroll
        for (int g = 0; g < 4; g++) {
            float res[4];
            #pragma unroll
            for (int k = 0; k < 4; k++) {
                const int s = 4 * g + k;
                float dp = p - lpl[s];
                float dq = q - lql[s];
                float T  = fmaf(uA, dp, -dq);
                float bT = __shfl_up_sync(0xffffffffu, T, 12);
                float S  = fmaf(uB, lpl[s] + wp, -(lql[s] + wq)) + bT;
                res[k] = lv[s] * S;
                uA += 1.f;
                uB += 1.f;
            }
            if (outv)
                *(float4*)(o + j0 + 4 * g) = *(const float4*)res;
        }
    }
}

extern "C" void kernel_launch(void* const* d_in, const int* in_sizes, int n_in,
                              void* d_out, int out_size)
{
    const float* left  = (const float*)d_in[0];
    const float* right = (const float*)d_in[1];
    float* out = (float*)d_out;
    dim3 grid(NROWS / 4, NSEG);
    stereo_win2_kernel<<<grid, NT>>>(left, right, out);
}

// round 14
// speedup vs baseline: 1.0744x; 1.0744x over previous
#include <cuda_runtime.h>

#define W_IMG  1248
#define NROWS  768
#define SEGW   320            // outputs per warp-segment
#define NSEG   4              // 4*320 = 1280 >= 1248, tail masked
#define HALO   192
#define NT     128            // 4 warps = 4 rows per CTA (same segment)
#define C      16             // elements per thread; 192 = 12*16 exactly

__global__ __launch_bounds__(NT) void stereo_win3_kernel(
    const float* __restrict__ L,
    const float* __restrict__ R,
    float* __restrict__ out)
{
    const int tid  = threadIdx.x;
    const int lane = tid & 31;
    const int warp = tid >> 5;
    const int row  = blockIdx.x * 4 + warp;   // 192*4 = 768 rows
    const int seg  = blockIdx.y;              // 0..3

    const float* __restrict__ r = R + (size_t)row * W_IMG;
    const float* __restrict__ l = L + (size_t)row * W_IMG;
    float* __restrict__ o = out + (size_t)row * W_IMG;

    const int u0 = lane * C;                  // local coord base (0..496)
    const int j0 = seg * SEGW - HALO + u0;    // global column of this chunk
    // whole-chunk predicates (all boundaries multiples of 16)
    const bool inr  = (j0 >= 0) && (j0 + C <= W_IMG);     // r-load validity
    const bool outv = (u0 >= HALO) && (j0 + C <= W_IMG);  // output validity

    // ---- ALL loads front-batched: 8 x LDG.128, MLP=8 ----
    float rv[C];
    if (inr) {
        #pragma unroll
        for (int v = 0; v < 4; v++)
            *(float4*)(rv + 4 * v) = *(const float4*)(r + j0 + 4 * v);
    } else {
        #pragma unroll
        for (int s = 0; s < C; s++) rv[s] = 0.f;
    }
    float lv[C];
    if (outv) {
        #pragma unroll
        for (int v = 0; v < 4; v++)
            *(float4*)(lv + 4 * v) = *(const float4*)(l + j0 + 4 * v);
    }

    // ---- chunk-LOCAL inclusive scan ----
    float lpl[C], lql[C];
    float p = 0.f, q = 0.f;
    {
        const float u0f = (float)u0;
        #pragma unroll
        for (int s = 0; s < C; s++) {
            p += rv[s];
            q = fmaf(u0f + (float)s, rv[s], q);
            lpl[s] = p;
            lql[s] = q;
        }
    }

    // ---- width-12 sliding-window sum of chunk totals (4-deep chain) ----
    // w12(k) = sum of (p,q) over lanes k-11..k  =  s8 + shfl_up(s4, 8)
    float s2p = p + __shfl_up_sync(0xffffffffu, p, 1);
    float s2q = q + __shfl_up_sync(0xffffffffu, q, 1);
    float s4p = s2p + __shfl_up_sync(0xffffffffu, s2p, 2);
    float s4q = s2q + __shfl_up_sync(0xffffffffu, s2q, 2);
    float s8p = s4p + __shfl_up_sync(0xffffffffu, s4p, 4);
    float s8q = s4q + __shfl_up_sync(0xffffffffu, s4q, 4);
    const float wp = s8p + __shfl_up_sync(0xffffffffu, s4p, 8) - p;  // 11 full chunks
    const float wq = s8q + __shfl_up_sync(0xffffffffu, s4q, 8) - q;

    // ---- outputs: own fragment + 11 full chunks + producer suffix ----
    // Producer (lane-12) term: T = u_cons*(p - lpl[s]) - (q - lql[s]),
    // u_cons = u0_prod + 192 + s.
    // Consumer: S = [uB*lpl - lql] + W + bT,  W(s) = uB(s)*wp - wq is an
    // arithmetic progression: W(s+1) = W(s) + wp  (one FADD per s).
    {
        const float cA = (float)(u0 + HALO);  // producer-side consumer coordinate
        const float cB = (float)u0;           // own coordinate base
        float W = fmaf(cB, wp, -wq);          // W(0)
        #pragma unroll
        for (int s = 0; s < C; s++) {
            float dp = p - lpl[s];
            float dq = q - lql[s];
            float T  = fmaf(cA + (float)s, dp, -dq);
            float bT = __shfl_up_sync(0xffffffffu, T, 12);
            float S  = fmaf(cB + (float)s, lpl[s], -lql[s]) + W + bT;
            lv[s] = lv[s] * S;
            W += wp;
        }
    }

    if (outv) {
        #pragma unroll
        for (int v = 0; v < 4; v++)
            *(float4*)(o + j0 + 4 * v) = *(const float4*)(lv + 4 * v);
    }
}

extern "C" void kernel_launch(void* const* d_in, const int* in_sizes, int n_in,
                              void* d_out, int out_size)
{
    const float* left  = (const float*)d_in[0];
    const float* right = (const float*)d_in[1];
    float* out = (float*)d_out;
    dim3 grid(NROWS / 4, NSEG);
    stereo_win3_kernel<<<grid, NT>>>(left, right, out);
}